// round 8
// baseline (speedup 1.0000x reference)
#include <cuda_runtime.h>
#include <cuda_bf16.h>
#include <math.h>
#include <stdint.h>

// Problem constants
#define BQ   4
#define TQ   256
#define DM   1024
#define NEXP 16
#define DL   64
#define NH   4
#define HD   16
#define NTOK 1024      // B*T
#define SEQL 17        // E+1
#define NASSIGN (NTOK*2)

// ---------------- scratch (device globals; no allocation allowed) ----------
__device__ float g_ef   [NTOK * 1024];        // (N, E*DL)  4 MB
__device__ float g_act  [NASSIGN * DL];       // gelu(sel)
__device__ float g_probs[NTOK * NEXP];
__device__ float g_tw   [NASSIGN];
__device__ int   g_ti   [NASSIGN];
__device__ float g_gctx [BQ * DL];
__device__ float g_gb   [BQ * NEXP];
__device__ int   g_ecnt [NEXP];
__device__ int   g_elist[NEXP * NTOK];
__device__ int   g_flat_a[NASSIGN];
__device__ int   g_flat_e[NASSIGN];
__device__ float g_xmp  [BQ][8][DM];
// bf16 split matrices for tensor-core GEMM
__device__ __nv_bfloat16 g_xhi[DM * DM];
__device__ __nv_bfloat16 g_xlo[DM * DM];
__device__ __nv_bfloat16 g_whi[DM * DM];
__device__ __nv_bfloat16 g_wlo[DM * DM];

__device__ __forceinline__ float gelu_f(float x) {
    return 0.5f * x * (1.0f + erff(x * 0.70710678118654752440f));
}
__device__ __forceinline__ uint32_t smem_u32(const void* p) {
    return (uint32_t)__cvta_generic_to_shared(p);
}
__device__ __forceinline__ void cp_async8(uint32_t dst, const void* src) {
    asm volatile("cp.async.ca.shared.global [%0], [%1], 8;"
                 :: "r"(dst), "l"(src) : "memory");
}
__device__ __forceinline__ void mma_bf16(float* c, const uint32_t* a, const uint32_t* b) {
    asm volatile(
        "mma.sync.aligned.m16n8k16.row.col.f32.bf16.bf16.f32 "
        "{%0,%1,%2,%3}, {%4,%5,%6,%7}, {%8,%9}, {%0,%1,%2,%3};"
        : "+f"(c[0]), "+f"(c[1]), "+f"(c[2]), "+f"(c[3])
        : "r"(a[0]), "r"(a[1]), "r"(a[2]), "r"(a[3]), "r"(b[0]), "r"(b[1]));
}
__device__ __forceinline__ float wsum(float v) {
    #pragma unroll
    for (int o = 16; o; o >>= 1) v += __shfl_xor_sync(0xffffffffu, v, o);
    return v;
}

// ---------------- K0: split X, W into bf16 hi/lo + zero g_ef --------------
__global__ void k_split(const float* __restrict__ X, const float* __restrict__ W)
{
    int i = blockIdx.x * 256 + threadIdx.x;     // float4 index over 2M floats
    // zero g_ef (needed for split-K atomic accumulation): 524288 float2 slots
    *(float2*)&g_ef[(size_t)i * 2] = make_float2(0.f, 0.f);

    const float4* src; __nv_bfloat16 *dh, *dl; int j;
    if (i < 262144) { src = (const float4*)X; dh = g_xhi; dl = g_xlo; j = i; }
    else            { src = (const float4*)W; dh = g_whi; dl = g_wlo; j = i - 262144; }
    float4 v = src[j];
    __nv_bfloat16 h0 = __float2bfloat16(v.x), h1 = __float2bfloat16(v.y);
    __nv_bfloat16 h2 = __float2bfloat16(v.z), h3 = __float2bfloat16(v.w);
    __nv_bfloat16 l0 = __float2bfloat16(v.x - __bfloat162float(h0));
    __nv_bfloat16 l1 = __float2bfloat16(v.y - __bfloat162float(h1));
    __nv_bfloat16 l2 = __float2bfloat16(v.z - __bfloat162float(h2));
    __nv_bfloat16 l3 = __float2bfloat16(v.w - __bfloat162float(h3));
    __nv_bfloat162 hA = __nv_bfloat162(h0, h1), hB = __nv_bfloat162(h2, h3);
    __nv_bfloat162 lA = __nv_bfloat162(l0, l1), lB = __nv_bfloat162(l2, l3);
    uint2 ho, lo;
    ho.x = *(uint32_t*)&hA; ho.y = *(uint32_t*)&hB;
    lo.x = *(uint32_t*)&lA; lo.y = *(uint32_t*)&lB;
    *(uint2*)(dh + (size_t)j * 4) = ho;
    *(uint2*)(dl + (size_t)j * 4) = lo;
}

// ---------------- K1a: partial sums for mean over T ------------------------
__global__ void k_mean(const float* __restrict__ x)
{
    int b = blockIdx.y, c = blockIdx.x;
    const float* p0 = x + ((size_t)b * TQ + c * 32) * DM;
    for (int d = threadIdx.x; d < DM; d += 256) {
        float s = 0.f;
        const float* p = p0 + d;
        #pragma unroll 8
        for (int t = 0; t < 32; ++t) s += p[(size_t)t * DM];
        g_xmp[b][c][d] = s;
    }
}

// ---------------- K1b: gctx + gb (per batch), zero expert counters ---------
__global__ void k_global(const float* __restrict__ gp_w, const float* __restrict__ gp_b,
                         const float* __restrict__ g1_w, const float* __restrict__ g1_b,
                         const float* __restrict__ g2_w, const float* __restrict__ g2_b)
{
    __shared__ float xm[DM];
    __shared__ float gctx[DL];
    __shared__ float g1s[128];
    __shared__ float part[256];
    int b = blockIdx.x, tid = threadIdx.x;
    if (b == 0 && tid < NEXP) g_ecnt[tid] = 0;

    for (int d = tid; d < DM; d += 256) {
        float s = 0.f;
        #pragma unroll
        for (int c = 0; c < 8; ++c) s += g_xmp[b][c][d];
        xm[d] = s * (1.0f / (float)TQ);
    }
    __syncthreads();

    {
        int j = tid >> 2, p = tid & 3;
        float s = 0.f;
        const float* w   = gp_w + (size_t)j * DM + p * 256;
        const float* xmp = xm + p * 256;
        #pragma unroll 4
        for (int d = 0; d < 256; ++d) s += xmp[d] * w[d];
        part[tid] = s;
    }
    __syncthreads();
    if (tid < DL) {
        float s = part[tid*4] + part[tid*4+1] + part[tid*4+2] + part[tid*4+3] + gp_b[tid];
        gctx[tid] = s;
        g_gctx[b * DL + tid] = s;
    }
    __syncthreads();

    if (tid < 128) {
        float s = g1_b[tid];
        const float* w = g1_w + tid * DL;
        #pragma unroll
        for (int d = 0; d < DL; ++d) s += gctx[d] * w[d];
        g1s[tid] = gelu_f(s);
    }
    __syncthreads();
    if (tid < NEXP) {
        float s = g2_b[tid];
        const float* w = g2_w + tid * 128;
        #pragma unroll
        for (int c = 0; c < 128; ++c) s += g1s[c] * w[c];
        g_gb[b * NEXP + tid] = s;
    }
}

// ---------------- K2: ef = X @ W^T via mma.sync bf16 hi/lo split -----------
// 64x64 CTA tile, 256 threads (2x4 warps, 32x16 per warp), BK=32, split-K=2,
// cp.async double buffer, smem rows padded to 40 bf16 (conflict-free).
// Each K-half atomicAdds its fp32 partial into g_ef (zeroed in k_split);
// exactly 2 commutative adds per element -> deterministic.
#define BK     32
#define TSTR   40
#define KHALF  16            // chunks per K-half (16*32 = 512)

__global__ void __launch_bounds__(256) k_ef_mma()
{
    __shared__ __nv_bfloat16 sm[2][4][64 * TSTR];   // [stage][Ahi,Alo,Bhi,Blo]

    int tid = threadIdx.x;
    int wid = tid >> 5, lane = tid & 31;
    int g = lane >> 2, t = lane & 3;
    int wm = (wid & 1) * 32, wn = (wid >> 1) * 16;
    int m0 = blockIdx.y * 64, n0 = blockIdx.x * 64;
    int kbase = blockIdx.z * (KHALF * BK);

    const __nv_bfloat16* tsrc[4] = {
        g_xhi + (size_t)m0 * DM + kbase, g_xlo + (size_t)m0 * DM + kbase,
        g_whi + (size_t)n0 * DM + kbase, g_wlo + (size_t)n0 * DM + kbase
    };

    float acc[2][2][4];
    #pragma unroll
    for (int mf = 0; mf < 2; ++mf)
        #pragma unroll
        for (int nf = 0; nf < 2; ++nf)
            #pragma unroll
            for (int q = 0; q < 4; ++q) acc[mf][nf][q] = 0.f;

    // --- async chunk loader: 4 tiles x 2 cp.async(8B) per thread ---
    auto issue = [&](int c, int bsel) {
        int k0 = c * BK;
        #pragma unroll
        for (int t4 = 0; t4 < 4; ++t4) {
            const __nv_bfloat16* src = tsrc[t4] + k0;
            #pragma unroll
            for (int j = 0; j < 2; ++j) {
                int idx = tid + j * 256;
                int r = idx >> 3, c8 = idx & 7;
                uint32_t dst = smem_u32(&sm[bsel][t4][r * TSTR + c8 * 4]);
                cp_async8(dst, src + (size_t)r * DM + c8 * 4);
            }
        }
    };

    issue(0, 0); asm volatile("cp.async.commit_group;" ::: "memory");
    issue(1, 1); asm volatile("cp.async.commit_group;" ::: "memory");

    for (int c = 0; c < KHALF; ++c) {
        int bsel = c & 1;
        asm volatile("cp.async.wait_group 1;" ::: "memory");
        __syncthreads();

        const __nv_bfloat16* Ah = sm[bsel][0];
        const __nv_bfloat16* Al = sm[bsel][1];
        const __nv_bfloat16* Bh = sm[bsel][2];
        const __nv_bfloat16* Bl = sm[bsel][3];

        #pragma unroll
        for (int kk = 0; kk < BK; kk += 16) {
            int col = kk + 2 * t;
            uint32_t ah[2][4], al[2][4], bh[2][2], bl[2][2];
            #pragma unroll
            for (int mf = 0; mf < 2; ++mf) {
                int r0 = wm + mf * 16 + g;
                ah[mf][0] = *(const uint32_t*)&Ah[(r0    ) * TSTR + col    ];
                ah[mf][1] = *(const uint32_t*)&Ah[(r0 + 8) * TSTR + col    ];
                ah[mf][2] = *(const uint32_t*)&Ah[(r0    ) * TSTR + col + 8];
                ah[mf][3] = *(const uint32_t*)&Ah[(r0 + 8) * TSTR + col + 8];
                al[mf][0] = *(const uint32_t*)&Al[(r0    ) * TSTR + col    ];
                al[mf][1] = *(const uint32_t*)&Al[(r0 + 8) * TSTR + col    ];
                al[mf][2] = *(const uint32_t*)&Al[(r0    ) * TSTR + col + 8];
                al[mf][3] = *(const uint32_t*)&Al[(r0 + 8) * TSTR + col + 8];
            }
            #pragma unroll
            for (int nf = 0; nf < 2; ++nf) {
                int r = wn + nf * 8 + g;
                bh[nf][0] = *(const uint32_t*)&Bh[r * TSTR + col    ];
                bh[nf][1] = *(const uint32_t*)&Bh[r * TSTR + col + 8];
                bl[nf][0] = *(const uint32_t*)&Bl[r * TSTR + col    ];
                bl[nf][1] = *(const uint32_t*)&Bl[r * TSTR + col + 8];
            }
            #pragma unroll
            for (int mf = 0; mf < 2; ++mf)
                #pragma unroll
                for (int nf = 0; nf < 2; ++nf) {
                    mma_bf16(acc[mf][nf], ah[mf], bh[nf]);
                    mma_bf16(acc[mf][nf], ah[mf], bl[nf]);
                    mma_bf16(acc[mf][nf], al[mf], bh[nf]);
                }
        }
        __syncthreads();
        if (c + 2 < KHALF) issue(c + 2, bsel);
        asm volatile("cp.async.commit_group;" ::: "memory");
    }

    // accumulate into g_ef (2 commutative adds/element across kz -> deterministic)
    #pragma unroll
    for (int mf = 0; mf < 2; ++mf) {
        int row = m0 + wm + mf * 16 + g;
        #pragma unroll
        for (int nf = 0; nf < 2; ++nf) {
            int col = n0 + wn + nf * 8 + 2 * t;
            atomicAdd(&g_ef[(size_t)(row    ) * DM + col    ], acc[mf][nf][0]);
            atomicAdd(&g_ef[(size_t)(row    ) * DM + col + 1], acc[mf][nf][1]);
            atomicAdd(&g_ef[(size_t)(row + 8) * DM + col    ], acc[mf][nf][2]);
            atomicAdd(&g_ef[(size_t)(row + 8) * DM + col + 1], acc[mf][nf][3]);
        }
    }
}

// ---------------- K3: per-token micro-transformer + routing ---------------
__global__ void __launch_bounds__(256)
k_token(const float* __restrict__ pos,
        const float* __restrict__ aw, const float* __restrict__ ab,
        const float* __restrict__ ow, const float* __restrict__ ob,
        const float* __restrict__ lnw, const float* __restrict__ lnb,
        const float* __restrict__ lsw, const float* __restrict__ lsb)
{
    __shared__ __align__(16) float seq[SEQL][DL];
    __shared__ __align__(16) float qkv[SEQL][192];
    __shared__ float sc[NH][SEQL][SEQL];
    __shared__ __align__(16) float ctx[SEQL][DL];
    __shared__ __align__(16) float hb[SEQL][DL];
    __shared__ float logits[NEXP];

    int n = blockIdx.x, tid = threadIdx.x;
    int b = n >> 8;

    for (int i = tid; i < NEXP * DL; i += 256)
        seq[1 + (i >> 6)][i & 63] = g_ef[(size_t)n * 1024 + i] + pos[i];
    if (tid < DL) seq[0][tid] = g_gctx[b * DL + tid];
    __syncthreads();

    // qkv: thread = output o; float4 over d, weight loaded once per u
    if (tid < 192) {
        float acc[SEQL];
        #pragma unroll
        for (int i = 0; i < SEQL; ++i) acc[i] = 0.f;
        const float4* w4 = (const float4*)(aw + tid * DL);
        #pragma unroll
        for (int u = 0; u < 16; ++u) {
            float4 wv = w4[u];
            #pragma unroll
            for (int i = 0; i < SEQL; ++i) {
                float4 sv = *(const float4*)&seq[i][u * 4];
                acc[i] += wv.x * sv.x + wv.y * sv.y + wv.z * sv.z + wv.w * sv.w;
            }
        }
        float bias = ab[tid];
        #pragma unroll
        for (int i = 0; i < SEQL; ++i) qkv[i][tid] = acc[i] + bias;
    }
    __syncthreads();

    // scores (float4 dot over head dim 16)
    for (int idx = tid; idx < NH * SEQL * SEQL; idx += 256) {
        int h = idx / (SEQL * SEQL);
        int r = idx % (SEQL * SEQL);
        int i = r / SEQL, j = r % SEQL;
        const float4* qp = (const float4*)&qkv[i][h * HD];
        const float4* kp = (const float4*)&qkv[j][64 + h * HD];
        float s = 0.f;
        #pragma unroll
        for (int u = 0; u < 4; ++u) {
            float4 qv = qp[u], kv = kp[u];
            s += qv.x * kv.x + qv.y * kv.y + qv.z * kv.z + qv.w * kv.w;
        }
        sc[h][i][j] = s * 0.25f;
    }
    __syncthreads();

    if (tid < NH * SEQL) {
        int h = tid / SEQL, i = tid % SEQL;
        float m = -1e30f;
        #pragma unroll
        for (int j = 0; j < SEQL; ++j) m = fmaxf(m, sc[h][i][j]);
        float sum = 0.f;
        #pragma unroll
        for (int j = 0; j < SEQL; ++j) { float e = expf(sc[h][i][j] - m); sc[h][i][j] = e; sum += e; }
        float inv = 1.0f / sum;
        #pragma unroll
        for (int j = 0; j < SEQL; ++j) sc[h][i][j] *= inv;
    }
    __syncthreads();

    for (int idx = tid; idx < SEQL * DL; idx += 256) {
        int i = idx >> 6, d = idx & 63, h = d >> 4;
        float s = 0.f;
        #pragma unroll
        for (int j = 0; j < SEQL; ++j) s += sc[h][i][j] * qkv[j][128 + d];
        ctx[i][d] = s;
    }
    __syncthreads();

    // attn_out + residual — all 256 threads over 17*64 outputs
    for (int idx = tid; idx < SEQL * DL; idx += 256) {
        int i = idx >> 6, d = idx & 63;
        const float4* w4 = (const float4*)(ow + d * DL);
        const float4* c4 = (const float4*)&ctx[i][0];
        float s = 0.f;
        #pragma unroll
        for (int u = 0; u < 16; ++u) {
            float4 wv = w4[u];
            float4 cv = c4[u];
            s += wv.x * cv.x + wv.y * cv.y + wv.z * cv.z + wv.w * cv.w;
        }
        hb[i][d] = s + ob[d] + seq[i][d];
    }
    __syncthreads();

    // layernorm rows 1..16 fused into local logit: warp per 2 rows
    {
        int w = tid >> 5, lane = tid & 31;
        #pragma unroll
        for (int rr = 0; rr < 2; ++rr) {
            int i = 1 + (w << 1) + rr;
            float v0 = hb[i][lane], v1 = hb[i][lane + 32];
            float mu = wsum(v0 + v1) * (1.0f / DL);
            float d0 = v0 - mu, d1 = v1 - mu;
            float var = wsum(d0 * d0 + d1 * d1) * (1.0f / DL);
            float rstd = rsqrtf(var + 1e-5f);
            float lp = (d0 * rstd * lnw[lane]      + lnb[lane])      * lsw[lane]
                     + (d1 * rstd * lnw[lane + 32] + lnb[lane + 32]) * lsw[lane + 32];
            lp = wsum(lp);
            if (lane == 0) logits[i - 1] = lp + lsb[0] + g_gb[b * NEXP + (i - 1)];
        }
    }
    __syncthreads();

    if (tid == 0) {
        float m = -1e30f;
        #pragma unroll
        for (int e = 0; e < NEXP; ++e) m = fmaxf(m, logits[e]);
        float p[NEXP]; float sum = 0.f;
        #pragma unroll
        for (int e = 0; e < NEXP; ++e) { p[e] = expf(logits[e] - m); sum += p[e]; }
        float inv = 1.0f / sum;
        float best = -1e30f, sec = -1e30f; int bi = 0, si = 0;
        #pragma unroll
        for (int e = 0; e < NEXP; ++e) {
            float pe = p[e] * inv;
            g_probs[n * NEXP + e] = pe;
            if (pe > best)      { sec = best; si = bi; best = pe; bi = e; }
            else if (pe > sec)  { sec = pe; si = e; }
        }
        float s2 = best + sec;
        g_tw[2*n]   = best / s2;
        g_tw[2*n+1] = sec  / s2;
        g_ti[2*n]   = bi;
        g_ti[2*n+1] = si;
        int p0 = atomicAdd(&g_ecnt[bi], 1); g_elist[bi * NTOK + p0] = 2*n;
        int p1 = atomicAdd(&g_ecnt[si], 1); g_elist[si * NTOK + p1] = 2*n + 1;
    }
    __syncthreads();

    if (tid < 2 * DL) {
        int k = tid >> 6, d = tid & 63;
        int e = g_ti[2*n + k];
        g_act[(size_t)(2*n + k) * DL + d] = gelu_f(g_ef[(size_t)n * 1024 + e * DL + d]);
    }
}

// ---------------- K3b: flatten expert lists (sorted by expert) -------------
__global__ void k_flat()
{
    __shared__ int off;
    int e = blockIdx.x;
    if (threadIdx.x == 0) {
        int o = 0;
        for (int i = 0; i < e; ++i) o += g_ecnt[i];
        off = o;
    }
    __syncthreads();
    int cnt = g_ecnt[e];
    for (int i = threadIdx.x; i < cnt; i += 256) {
        g_flat_a[off + i] = g_elist[e * NTOK + i];
        g_flat_e[off + i] = e;
    }
}

// ---------------- K4: flat-tile expert up-projection -> atomicAdd out ------
// grid (NASSIGN/16 = 128 tiles, 16 m-tiles). Exactly 2 adds per out element
// (fp add is commutative with 2 operands -> deterministic).
__global__ void __launch_bounds__(256)
k_moe2(const float* __restrict__ w_up, float* __restrict__ out)
{
    __shared__ float acts[16][DL];
    __shared__ float wt[DL][64];
    __shared__ int sa[16];
    __shared__ int se[16];
    int tid = threadIdx.x;
    int base = blockIdx.x * 16;
    int m0 = blockIdx.y * 64;

    if (tid < 16) { sa[tid] = g_flat_a[base + tid]; se[tid] = g_flat_e[base + tid]; }
    __syncthreads();
    #pragma unroll
    for (int j = 0; j < 4; ++j) {
        int i = tid + j * 256;
        acts[i >> 6][i & 63] = g_act[(size_t)sa[i >> 6] * DL + (i & 63)];
    }
    __syncthreads();

    int s = 0;
    while (s < 16) {
        int e = se[s];
        int r = s + 1;
        while (r < 16 && se[r] == e) ++r;
        __syncthreads();   // protect previous wt use
        #pragma unroll
        for (int j = 0; j < 16; ++j) {
            int idx = tid + j * 256;
            int d = idx >> 6, cc = idx & 63;
            wt[d][cc] = w_up[(((size_t)e << 6) + d) * 1024 + m0 + cc];
        }
        __syncthreads();
        for (int t0 = s; t0 < r; t0 += 4) {
            int t = t0 + (tid >> 6);
            if (t < r) {
                int col = tid & 63;
                float sum = 0.f;
                #pragma unroll
                for (int d = 0; d < DL; ++d) sum += acts[t][d] * wt[d][col];
                int a = sa[t];
                atomicAdd(&out[(size_t)(a >> 1) * 1024 + m0 + col], g_tw[a] * sum);
            }
        }
        s = r;
    }
}

// ---------------- K6: aux loss (deterministic reduction) -------------------
__global__ void k_aux(float* __restrict__ out)
{
    __shared__ float partial[NEXP];
    int tid = threadIdx.x;                      // 512 = 16 warps
    int w = tid >> 5, lane = tid & 31;
    float psum = 0.f; int ccnt = 0;
    for (int n = lane; n < NTOK; n += 32) {
        psum += g_probs[n * NEXP + w];
        ccnt += (g_ti[2*n] == w) + (g_ti[2*n+1] == w);
    }
    #pragma unroll
    for (int o = 16; o; o >>= 1) {
        psum += __shfl_down_sync(0xffffffff, psum, o);
        ccnt += __shfl_down_sync(0xffffffff, ccnt, o);
    }
    if (lane == 0) partial[w] = psum * (float)ccnt;
    __syncthreads();
    if (tid == 0) {
        float s = 0.f;
        #pragma unroll
        for (int e = 0; e < NEXP; ++e) s += partial[e];
        out[NTOK * 1024] = s * ((float)NEXP / ((float)NTOK * (float)NTOK));
    }
}

// ---------------- launch ---------------------------------------------------
extern "C" void kernel_launch(void* const* d_in, const int* in_sizes, int n_in,
                              void* d_out, int out_size)
{
    const float* x      = (const float*)d_in[0];
    const float* w_down = (const float*)d_in[1];
    const float* pos    = (const float*)d_in[2];
    const float* gp_w   = (const float*)d_in[3];
    const float* gp_b   = (const float*)d_in[4];
    const float* aw     = (const float*)d_in[5];
    const float* ab     = (const float*)d_in[6];
    const float* ow     = (const float*)d_in[7];
    const float* ob     = (const float*)d_in[8];
    const float* lnw    = (const float*)d_in[9];
    const float* lnb    = (const float*)d_in[10];
    const float* lsw    = (const float*)d_in[11];
    const float* lsb    = (const float*)d_in[12];
    const float* g1w    = (const float*)d_in[13];
    const float* g1b    = (const float*)d_in[14];
    const float* g2w    = (const float*)d_in[15];
    const float* g2b    = (const float*)d_in[16];
    const float* wup    = (const float*)d_in[17];
    float* out = (float*)d_out;

    cudaMemsetAsync(d_out, 0, (size_t)out_size * sizeof(float));
    k_split  <<<2048, 256>>>(x, w_down);
    k_mean   <<<dim3(8, BQ), 256>>>(x);
    k_global <<<BQ, 256>>>(gp_w, gp_b, g1w, g1b, g2w, g2b);
    k_ef_mma <<<dim3(16, 16, 2), 256>>>();
    k_token  <<<NTOK, 256>>>(pos, aw, ab, ow, ob, lnw, lnb, lsw, lsb);
    k_flat   <<<NEXP, 256>>>();
    k_moe2   <<<dim3(NASSIGN / 16, 16), 256>>>(wup, out);
    if (out_size > NTOK * 1024) k_aux<<<1, 512>>>(out);
}

// round 9
// speedup vs baseline: 1.0599x; 1.0599x over previous
#include <cuda_runtime.h>
#include <cuda_bf16.h>
#include <math.h>
#include <stdint.h>

// Problem constants
#define BQ   4
#define TQ   256
#define DM   1024
#define NEXP 16
#define DL   64
#define NH   4
#define HD   16
#define NTOK 1024      // B*T
#define SEQL 17        // E+1
#define NASSIGN (NTOK*2)

// ---------------- scratch (device globals; no allocation allowed) ----------
__device__ float g_ef   [NTOK * 1024];        // (N, E*DL)  4 MB
__device__ float g_act  [NASSIGN * DL];       // gelu(sel)
__device__ float g_probs[NTOK * NEXP];
__device__ float g_tw   [NASSIGN];
__device__ int   g_ti   [NASSIGN];
__device__ float g_gctx [BQ * DL];
__device__ float g_gb   [BQ * NEXP];
__device__ int   g_ecnt [NEXP];
__device__ int   g_elist[NEXP * NTOK];
__device__ int   g_flat_a[NASSIGN];
__device__ int   g_flat_e[NASSIGN];
__device__ float g_xmp  [BQ][8][DM];
// bf16 split matrices for tensor-core GEMM
__device__ __nv_bfloat16 g_xhi[DM * DM];
__device__ __nv_bfloat16 g_xlo[DM * DM];
__device__ __nv_bfloat16 g_whi[DM * DM];
__device__ __nv_bfloat16 g_wlo[DM * DM];

__device__ __forceinline__ float gelu_f(float x) {
    return 0.5f * x * (1.0f + erff(x * 0.70710678118654752440f));
}
__device__ __forceinline__ uint32_t smem_u32(const void* p) {
    return (uint32_t)__cvta_generic_to_shared(p);
}
__device__ __forceinline__ void cp_async8(uint32_t dst, const void* src) {
    asm volatile("cp.async.ca.shared.global [%0], [%1], 8;"
                 :: "r"(dst), "l"(src) : "memory");
}
__device__ __forceinline__ void mma_bf16(float* c, const uint32_t* a,
                                         uint32_t b0, uint32_t b1) {
    asm volatile(
        "mma.sync.aligned.m16n8k16.row.col.f32.bf16.bf16.f32 "
        "{%0,%1,%2,%3}, {%4,%5,%6,%7}, {%8,%9}, {%0,%1,%2,%3};"
        : "+f"(c[0]), "+f"(c[1]), "+f"(c[2]), "+f"(c[3])
        : "r"(a[0]), "r"(a[1]), "r"(a[2]), "r"(a[3]), "r"(b0), "r"(b1));
}
__device__ __forceinline__ void ldsm4(uint32_t* r, uint32_t addr) {
    asm volatile("ldmatrix.sync.aligned.m8n8.x4.shared.b16 {%0,%1,%2,%3}, [%4];"
                 : "=r"(r[0]), "=r"(r[1]), "=r"(r[2]), "=r"(r[3]) : "r"(addr));
}

// ---------------- K0: split X, W into bf16 hi/lo + zero g_ef --------------
__global__ void k_split(const float* __restrict__ X, const float* __restrict__ W)
{
    int i = blockIdx.x * 256 + threadIdx.x;     // float4 index over 2M floats
    // zero g_ef (split-K atomic accumulation target): 524288 float2 slots
    *(float2*)&g_ef[(size_t)i * 2] = make_float2(0.f, 0.f);

    const float4* src; __nv_bfloat16 *dh, *dl; int j;
    if (i < 262144) { src = (const float4*)X; dh = g_xhi; dl = g_xlo; j = i; }
    else            { src = (const float4*)W; dh = g_whi; dl = g_wlo; j = i - 262144; }
    float4 v = src[j];
    __nv_bfloat16 h0 = __float2bfloat16(v.x), h1 = __float2bfloat16(v.y);
    __nv_bfloat16 h2 = __float2bfloat16(v.z), h3 = __float2bfloat16(v.w);
    __nv_bfloat16 l0 = __float2bfloat16(v.x - __bfloat162float(h0));
    __nv_bfloat16 l1 = __float2bfloat16(v.y - __bfloat162float(h1));
    __nv_bfloat16 l2 = __float2bfloat16(v.z - __bfloat162float(h2));
    __nv_bfloat16 l3 = __float2bfloat16(v.w - __bfloat162float(h3));
    __nv_bfloat162 hA = __nv_bfloat162(h0, h1), hB = __nv_bfloat162(h2, h3);
    __nv_bfloat162 lA = __nv_bfloat162(l0, l1), lB = __nv_bfloat162(l2, l3);
    uint2 ho, lo;
    ho.x = *(uint32_t*)&hA; ho.y = *(uint32_t*)&hB;
    lo.x = *(uint32_t*)&lA; lo.y = *(uint32_t*)&lB;
    *(uint2*)(dh + (size_t)j * 4) = ho;
    *(uint2*)(dl + (size_t)j * 4) = lo;
}

// ---------------- K1a: partial sums for mean over T ------------------------
__global__ void k_mean(const float* __restrict__ x)
{
    int b = blockIdx.y, c = blockIdx.x;
    const float* p0 = x + ((size_t)b * TQ + c * 32) * DM;
    for (int d = threadIdx.x; d < DM; d += 256) {
        float s = 0.f;
        const float* p = p0 + d;
        #pragma unroll 8
        for (int t = 0; t < 32; ++t) s += p[(size_t)t * DM];
        g_xmp[b][c][d] = s;
    }
}

// ---------------- K1b: gctx + gb (per batch), zero expert counters ---------
__global__ void k_global(const float* __restrict__ gp_w, const float* __restrict__ gp_b,
                         const float* __restrict__ g1_w, const float* __restrict__ g1_b,
                         const float* __restrict__ g2_w, const float* __restrict__ g2_b)
{
    __shared__ float xm[DM];
    __shared__ float gctx[DL];
    __shared__ float g1s[128];
    __shared__ float part[256];
    int b = blockIdx.x, tid = threadIdx.x;
    if (b == 0 && tid < NEXP) g_ecnt[tid] = 0;

    for (int d = tid; d < DM; d += 256) {
        float s = 0.f;
        #pragma unroll
        for (int c = 0; c < 8; ++c) s += g_xmp[b][c][d];
        xm[d] = s * (1.0f / (float)TQ);
    }
    __syncthreads();

    {
        int j = tid >> 2, p = tid & 3;
        float s = 0.f;
        const float* w   = gp_w + (size_t)j * DM + p * 256;
        const float* xmp = xm + p * 256;
        #pragma unroll 4
        for (int d = 0; d < 256; ++d) s += xmp[d] * w[d];
        part[tid] = s;
    }
    __syncthreads();
    if (tid < DL) {
        float s = part[tid*4] + part[tid*4+1] + part[tid*4+2] + part[tid*4+3] + gp_b[tid];
        gctx[tid] = s;
        g_gctx[b * DL + tid] = s;
    }
    __syncthreads();

    if (tid < 128) {
        float s = g1_b[tid];
        const float* w = g1_w + tid * DL;
        #pragma unroll
        for (int d = 0; d < DL; ++d) s += gctx[d] * w[d];
        g1s[tid] = gelu_f(s);
    }
    __syncthreads();
    if (tid < NEXP) {
        float s = g2_b[tid];
        const float* w = g2_w + tid * 128;
        #pragma unroll
        for (int c = 0; c < 128; ++c) s += g1s[c] * w[c];
        g_gb[b * NEXP + tid] = s;
    }
}

// ---------------- K2: ef = X @ W^T via mma.sync bf16 hi/lo split -----------
// 64x64 CTA tile, 128 threads (2x2 warps, 32x32 per warp), BK=32, split-K=2,
// ldmatrix.x4 fragment loads, cp.async double buffer, rows padded to 40 bf16
// (80B row stride: 16B-aligned, conflict-free for ldmatrix).
// Each K-half atomicAdds into g_ef (zeroed in k_split); exactly 2 commutative
// adds per element -> deterministic.
#define BK     32
#define TSTR   40
#define KHALF  16            // chunks per K-half (16*32 = 512)

__global__ void __launch_bounds__(128) k_ef_mma()
{
    __shared__ __nv_bfloat16 sm[2][4][64 * TSTR];   // [stage][Ahi,Alo,Bhi,Blo]

    int tid = threadIdx.x;
    int wid = tid >> 5, lane = tid & 31;
    int g = lane >> 2, t = lane & 3;
    int wm = (wid & 1) * 32, wn = (wid >> 1) * 32;
    int m0 = blockIdx.y * 64, n0 = blockIdx.x * 64;
    int kbase = blockIdx.z * (KHALF * BK);

    // ldmatrix per-lane byte offset within a tile: row = lane&15, col-half = (lane>>4)*8
    int loff = ((lane & 15) * TSTR + (lane >> 4) * 8) * 2;

    const __nv_bfloat16* tsrc[4] = {
        g_xhi + (size_t)m0 * DM + kbase, g_xlo + (size_t)m0 * DM + kbase,
        g_whi + (size_t)n0 * DM + kbase, g_wlo + (size_t)n0 * DM + kbase
    };

    float acc[2][4][4];
    #pragma unroll
    for (int mf = 0; mf < 2; ++mf)
        #pragma unroll
        for (int nf = 0; nf < 4; ++nf)
            #pragma unroll
            for (int q = 0; q < 4; ++q) acc[mf][nf][q] = 0.f;

    // --- async chunk loader: 4 tiles x 4 cp.async(8B) per thread ---
    auto issue = [&](int c, int bsel) {
        int k0 = c * BK;
        #pragma unroll
        for (int t4 = 0; t4 < 4; ++t4) {
            const __nv_bfloat16* src = tsrc[t4] + k0;
            #pragma unroll
            for (int j = 0; j < 4; ++j) {
                int idx = tid + j * 128;
                int r = idx >> 3, c8 = idx & 7;
                uint32_t dst = smem_u32(&sm[bsel][t4][r * TSTR + c8 * 4]);
                cp_async8(dst, src + (size_t)r * DM + c8 * 4);
            }
        }
    };

    issue(0, 0); asm volatile("cp.async.commit_group;" ::: "memory");
    issue(1, 1); asm volatile("cp.async.commit_group;" ::: "memory");

    for (int c = 0; c < KHALF; ++c) {
        int bsel = c & 1;
        asm volatile("cp.async.wait_group 1;" ::: "memory");
        __syncthreads();

        uint32_t baseAh = smem_u32(&sm[bsel][0][0]) + loff;
        uint32_t baseAl = smem_u32(&sm[bsel][1][0]) + loff;
        uint32_t baseBh = smem_u32(&sm[bsel][2][0]) + loff;
        uint32_t baseBl = smem_u32(&sm[bsel][3][0]) + loff;

        #pragma unroll
        for (int kk = 0; kk < BK; kk += 16) {
            uint32_t ah[2][4], al[2][4], bh[2][4], bl[2][4];
            #pragma unroll
            for (int mf = 0; mf < 2; ++mf) {
                uint32_t ro = ((wm + mf * 16) * TSTR + kk) * 2;
                ldsm4(ah[mf], baseAh + ro);
                ldsm4(al[mf], baseAl + ro);
            }
            #pragma unroll
            for (int G = 0; G < 2; ++G) {
                uint32_t ro = ((wn + G * 16) * TSTR + kk) * 2;
                ldsm4(bh[G], baseBh + ro);
                ldsm4(bl[G], baseBl + ro);
            }
            #pragma unroll
            for (int mf = 0; mf < 2; ++mf)
                #pragma unroll
                for (int nf = 0; nf < 4; ++nf) {
                    int G = nf >> 1, o = nf & 1;
                    mma_bf16(acc[mf][nf], ah[mf], bh[G][o], bh[G][o + 2]);
                    mma_bf16(acc[mf][nf], ah[mf], bl[G][o], bl[G][o + 2]);
                    mma_bf16(acc[mf][nf], al[mf], bh[G][o], bh[G][o + 2]);
                }
        }
        __syncthreads();
        if (c + 2 < KHALF) issue(c + 2, bsel);
        asm volatile("cp.async.commit_group;" ::: "memory");
    }

    // accumulate into g_ef (2 commutative adds/element across kz -> deterministic)
    #pragma unroll
    for (int mf = 0; mf < 2; ++mf) {
        int row = m0 + wm + mf * 16 + g;
        #pragma unroll
        for (int nf = 0; nf < 4; ++nf) {
            int col = n0 + wn + nf * 8 + 2 * t;
            atomicAdd(&g_ef[(size_t)(row    ) * DM + col    ], acc[mf][nf][0]);
            atomicAdd(&g_ef[(size_t)(row    ) * DM + col + 1], acc[mf][nf][1]);
            atomicAdd(&g_ef[(size_t)(row + 8) * DM + col    ], acc[mf][nf][2]);
            atomicAdd(&g_ef[(size_t)(row + 8) * DM + col + 1], acc[mf][nf][3]);
        }
    }
}

// ---------------- K3: per-token micro-transformer + routing (R7 version) ---
__global__ void __launch_bounds__(256)
k_token(const float* __restrict__ pos,
        const float* __restrict__ aw, const float* __restrict__ ab,
        const float* __restrict__ ow, const float* __restrict__ ob,
        const float* __restrict__ lnw, const float* __restrict__ lnb,
        const float* __restrict__ lsw, const float* __restrict__ lsb)
{
    __shared__ __align__(16) float seq[SEQL][DL];
    __shared__ __align__(16) float qkv[SEQL][192];
    __shared__ float sc[NH][SEQL][SEQL];
    __shared__ __align__(16) float ctx[SEQL][DL];
    __shared__ float hb[SEQL][DL];
    __shared__ float logits[NEXP];

    int n = blockIdx.x, tid = threadIdx.x;
    int b = n >> 8;

    for (int i = tid; i < NEXP * DL; i += 256)
        seq[1 + (i >> 6)][i & 63] = g_ef[(size_t)n * 1024 + i] + pos[i];
    if (tid < DL) seq[0][tid] = g_gctx[b * DL + tid];
    __syncthreads();

    // qkv: thread = output o; float4 over d, weight loaded once per u
    if (tid < 192) {
        float acc[SEQL];
        #pragma unroll
        for (int i = 0; i < SEQL; ++i) acc[i] = 0.f;
        const float4* w4 = (const float4*)(aw + tid * DL);
        #pragma unroll
        for (int u = 0; u < 16; ++u) {
            float4 wv = w4[u];
            #pragma unroll
            for (int i = 0; i < SEQL; ++i) {
                float4 sv = *(const float4*)&seq[i][u * 4];
                acc[i] += wv.x * sv.x + wv.y * sv.y + wv.z * sv.z + wv.w * sv.w;
            }
        }
        float bias = ab[tid];
        #pragma unroll
        for (int i = 0; i < SEQL; ++i) qkv[i][tid] = acc[i] + bias;
    }
    __syncthreads();

    // scores (float4 dot over head dim 16)
    for (int idx = tid; idx < NH * SEQL * SEQL; idx += 256) {
        int h = idx / (SEQL * SEQL);
        int r = idx % (SEQL * SEQL);
        int i = r / SEQL, j = r % SEQL;
        const float4* qp = (const float4*)&qkv[i][h * HD];
        const float4* kp = (const float4*)&qkv[j][64 + h * HD];
        float s = 0.f;
        #pragma unroll
        for (int u = 0; u < 4; ++u) {
            float4 qv = qp[u], kv = kp[u];
            s += qv.x * kv.x + qv.y * kv.y + qv.z * kv.z + qv.w * kv.w;
        }
        sc[h][i][j] = s * 0.25f;
    }
    __syncthreads();

    if (tid < NH * SEQL) {
        int h = tid / SEQL, i = tid % SEQL;
        float m = -1e30f;
        #pragma unroll
        for (int j = 0; j < SEQL; ++j) m = fmaxf(m, sc[h][i][j]);
        float sum = 0.f;
        #pragma unroll
        for (int j = 0; j < SEQL; ++j) { float e = expf(sc[h][i][j] - m); sc[h][i][j] = e; sum += e; }
        float inv = 1.0f / sum;
        #pragma unroll
        for (int j = 0; j < SEQL; ++j) sc[h][i][j] *= inv;
    }
    __syncthreads();

    for (int idx = tid; idx < SEQL * DL; idx += 256) {
        int i = idx >> 6, d = idx & 63, h = d >> 4;
        float s = 0.f;
        #pragma unroll
        for (int j = 0; j < SEQL; ++j) s += sc[h][i][j] * qkv[j][128 + d];
        ctx[i][d] = s;
    }
    __syncthreads();

    // attn_out + residual (thread = output d, acc over 17 rows; weights cached)
    if (tid < DL) {
        float acc[SEQL];
        #pragma unroll
        for (int i = 0; i < SEQL; ++i) acc[i] = 0.f;
        const float4* w4 = (const float4*)(ow + tid * DL);
        #pragma unroll
        for (int u = 0; u < 16; ++u) {
            float4 wv = w4[u];
            #pragma unroll
            for (int i = 0; i < SEQL; ++i) {
                float4 cv = *(const float4*)&ctx[i][u * 4];
                acc[i] += wv.x * cv.x + wv.y * cv.y + wv.z * cv.z + wv.w * cv.w;
            }
        }
        float bias = ob[tid];
        #pragma unroll
        for (int i = 0; i < SEQL; ++i) hb[i][tid] = acc[i] + bias + seq[i][tid];
    }
    __syncthreads();

    if (tid < NEXP) {
        int i = 1 + tid;
        float mu = 0.f;
        #pragma unroll
        for (int d = 0; d < DL; ++d) mu += hb[i][d];
        mu *= (1.0f / DL);
        float var = 0.f;
        #pragma unroll
        for (int d = 0; d < DL; ++d) { float t2 = hb[i][d] - mu; var += t2 * t2; }
        var *= (1.0f / DL);
        float rstd = rsqrtf(var + 1e-5f);
        float lg = lsb[0];
        #pragma unroll
        for (int d = 0; d < DL; ++d)
            lg += ((hb[i][d] - mu) * rstd * lnw[d] + lnb[d]) * lsw[d];
        logits[tid] = lg + g_gb[b * NEXP + tid];
    }
    __syncthreads();

    if (tid == 0) {
        float m = -1e30f;
        #pragma unroll
        for (int e = 0; e < NEXP; ++e) m = fmaxf(m, logits[e]);
        float p[NEXP]; float sum = 0.f;
        #pragma unroll
        for (int e = 0; e < NEXP; ++e) { p[e] = expf(logits[e] - m); sum += p[e]; }
        float inv = 1.0f / sum;
        float best = -1e30f, sec = -1e30f; int bi = 0, si = 0;
        #pragma unroll
        for (int e = 0; e < NEXP; ++e) {
            float pe = p[e] * inv;
            g_probs[n * NEXP + e] = pe;
            if (pe > best)      { sec = best; si = bi; best = pe; bi = e; }
            else if (pe > sec)  { sec = pe; si = e; }
        }
        float s2 = best + sec;
        g_tw[2*n]   = best / s2;
        g_tw[2*n+1] = sec  / s2;
        g_ti[2*n]   = bi;
        g_ti[2*n+1] = si;
        int p0 = atomicAdd(&g_ecnt[bi], 1); g_elist[bi * NTOK + p0] = 2*n;
        int p1 = atomicAdd(&g_ecnt[si], 1); g_elist[si * NTOK + p1] = 2*n + 1;
    }
    __syncthreads();

    if (tid < 2 * DL) {
        int k = tid >> 6, d = tid & 63;
        int e = g_ti[2*n + k];
        g_act[(size_t)(2*n + k) * DL + d] = gelu_f(g_ef[(size_t)n * 1024 + e * DL + d]);
    }
}

// ---------------- K3b: flatten expert lists (sorted by expert) -------------
__global__ void k_flat()
{
    __shared__ int off;
    int e = blockIdx.x;
    if (threadIdx.x == 0) {
        int o = 0;
        for (int i = 0; i < e; ++i) o += g_ecnt[i];
        off = o;
    }
    __syncthreads();
    int cnt = g_ecnt[e];
    for (int i = threadIdx.x; i < cnt; i += 256) {
        g_flat_a[off + i] = g_elist[e * NTOK + i];
        g_flat_e[off + i] = e;
    }
}

// ---------------- K4: flat-tile expert up-projection -> atomicAdd out ------
__global__ void __launch_bounds__(256)
k_moe2(const float* __restrict__ w_up, float* __restrict__ out)
{
    __shared__ float acts[16][DL];
    __shared__ float wt[DL][64];
    __shared__ int sa[16];
    __shared__ int se[16];
    int tid = threadIdx.x;
    int base = blockIdx.x * 16;
    int m0 = blockIdx.y * 64;

    if (tid < 16) { sa[tid] = g_flat_a[base + tid]; se[tid] = g_flat_e[base + tid]; }
    __syncthreads();
    #pragma unroll
    for (int j = 0; j < 4; ++j) {
        int i = tid + j * 256;
        acts[i >> 6][i & 63] = g_act[(size_t)sa[i >> 6] * DL + (i & 63)];
    }
    __syncthreads();

    int s = 0;
    while (s < 16) {
        int e = se[s];
        int r = s + 1;
        while (r < 16 && se[r] == e) ++r;
        __syncthreads();   // protect previous wt use
        #pragma unroll
        for (int j = 0; j < 16; ++j) {
            int idx = tid + j * 256;
            int d = idx >> 6, cc = idx & 63;
            wt[d][cc] = w_up[(((size_t)e << 6) + d) * 1024 + m0 + cc];
        }
        __syncthreads();
        for (int t0 = s; t0 < r; t0 += 4) {
            int t = t0 + (tid >> 6);
            if (t < r) {
                int col = tid & 63;
                float sum = 0.f;
                #pragma unroll
                for (int d = 0; d < DL; ++d) sum += acts[t][d] * wt[d][col];
                int a = sa[t];
                atomicAdd(&out[(size_t)(a >> 1) * 1024 + m0 + col], g_tw[a] * sum);
            }
        }
        s = r;
    }
}

// ---------------- K6: aux loss (deterministic reduction) -------------------
__global__ void k_aux(float* __restrict__ out)
{
    __shared__ float partial[NEXP];
    int tid = threadIdx.x;                      // 512 = 16 warps
    int w = tid >> 5, lane = tid & 31;
    float psum = 0.f; int ccnt = 0;
    for (int n = lane; n < NTOK; n += 32) {
        psum += g_probs[n * NEXP + w];
        ccnt += (g_ti[2*n] == w) + (g_ti[2*n+1] == w);
    }
    #pragma unroll
    for (int o = 16; o; o >>= 1) {
        psum += __shfl_down_sync(0xffffffff, psum, o);
        ccnt += __shfl_down_sync(0xffffffff, ccnt, o);
    }
    if (lane == 0) partial[w] = psum * (float)ccnt;
    __syncthreads();
    if (tid == 0) {
        float s = 0.f;
        #pragma unroll
        for (int e = 0; e < NEXP; ++e) s += partial[e];
        out[NTOK * 1024] = s * ((float)NEXP / ((float)NTOK * (float)NTOK));
    }
}

// ---------------- launch ---------------------------------------------------
extern "C" void kernel_launch(void* const* d_in, const int* in_sizes, int n_in,
                              void* d_out, int out_size)
{
    const float* x      = (const float*)d_in[0];
    const float* w_down = (const float*)d_in[1];
    const float* pos    = (const float*)d_in[2];
    const float* gp_w   = (const float*)d_in[3];
    const float* gp_b   = (const float*)d_in[4];
    const float* aw     = (const float*)d_in[5];
    const float* ab     = (const float*)d_in[6];
    const float* ow     = (const float*)d_in[7];
    const float* ob     = (const float*)d_in[8];
    const float* lnw    = (const float*)d_in[9];
    const float* lnb    = (const float*)d_in[10];
    const float* lsw    = (const float*)d_in[11];
    const float* lsb    = (const float*)d_in[12];
    const float* g1w    = (const float*)d_in[13];
    const float* g1b    = (const float*)d_in[14];
    const float* g2w    = (const float*)d_in[15];
    const float* g2b    = (const float*)d_in[16];
    const float* wup    = (const float*)d_in[17];
    float* out = (float*)d_out;

    cudaMemsetAsync(d_out, 0, (size_t)out_size * sizeof(float));
    k_split  <<<2048, 256>>>(x, w_down);
    k_mean   <<<dim3(8, BQ), 256>>>(x);
    k_global <<<BQ, 256>>>(gp_w, gp_b, g1w, g1b, g2w, g2b);
    k_ef_mma <<<dim3(16, 16, 2), 128>>>();
    k_token  <<<NTOK, 256>>>(pos, aw, ab, ow, ob, lnw, lnb, lsw, lsb);
    k_flat   <<<NEXP, 256>>>();
    k_moe2   <<<dim3(NASSIGN / 16, 16), 256>>>(wup, out);
    if (out_size > NTOK * 1024) k_aux<<<1, 512>>>(out);
}

// round 10
// speedup vs baseline: 1.2624x; 1.1911x over previous
#include <cuda_runtime.h>
#include <cuda_bf16.h>
#include <math.h>
#include <stdint.h>

// Problem constants
#define BQ   4
#define TQ   256
#define DM   1024
#define NEXP 16
#define DL   64
#define NH   4
#define HD   16
#define NTOK 1024      // B*T
#define SEQL 17        // E+1
#define NASSIGN (NTOK*2)

// ---------------- scratch (device globals; no allocation allowed) ----------
__device__ float g_ef   [NTOK * 1024];
__device__ float g_act  [NASSIGN * DL];
__device__ float g_probs[NTOK * NEXP];
__device__ float g_tw   [NASSIGN];
__device__ int   g_ti   [NASSIGN];
__device__ float g_gctx [BQ * DL];
__device__ float g_gb   [BQ * NEXP];
__device__ int   g_ecnt [NEXP];
__device__ int   g_elist[NEXP * NTOK];
__device__ int   g_flat_a[NASSIGN];
__device__ int   g_flat_e[NASSIGN];
__device__ float g_xmp  [BQ][8][DM];
__device__ __nv_bfloat16 g_xhi[DM * DM];
__device__ __nv_bfloat16 g_xlo[DM * DM];
__device__ __nv_bfloat16 g_whi[DM * DM];
__device__ __nv_bfloat16 g_wlo[DM * DM];

__device__ __forceinline__ float gelu_f(float x) {
    return 0.5f * x * (1.0f + erff(x * 0.70710678118654752440f));
}
__device__ __forceinline__ uint32_t smem_u32(const void* p) {
    return (uint32_t)__cvta_generic_to_shared(p);
}
__device__ __forceinline__ void cp_async8(uint32_t dst, const void* src) {
    asm volatile("cp.async.ca.shared.global [%0], [%1], 8;"
                 :: "r"(dst), "l"(src) : "memory");
}
__device__ __forceinline__ void mma_bf16(float* c, const uint32_t* a,
                                         uint32_t b0, uint32_t b1) {
    asm volatile(
        "mma.sync.aligned.m16n8k16.row.col.f32.bf16.bf16.f32 "
        "{%0,%1,%2,%3}, {%4,%5,%6,%7}, {%8,%9}, {%0,%1,%2,%3};"
        : "+f"(c[0]), "+f"(c[1]), "+f"(c[2]), "+f"(c[3])
        : "r"(a[0]), "r"(a[1]), "r"(a[2]), "r"(a[3]), "r"(b0), "r"(b1));
}
__device__ __forceinline__ void ldsm4(uint32_t* r, uint32_t addr) {
    asm volatile("ldmatrix.sync.aligned.m8n8.x4.shared.b16 {%0,%1,%2,%3}, [%4];"
                 : "=r"(r[0]), "=r"(r[1]), "=r"(r[2]), "=r"(r[3]) : "r"(addr));
}
__device__ __forceinline__ float wsum(float v) {
    #pragma unroll
    for (int o = 16; o; o >>= 1) v += __shfl_xor_sync(0xffffffffu, v, o);
    return v;
}

// ---------------- K0: split X,W into bf16 hi/lo + zero g_ef + mean partials
__global__ void k_split(const float* __restrict__ X, const float* __restrict__ W)
{
    int tid = threadIdx.x;
    int i = blockIdx.x * 256 + tid;
    *(float2*)&g_ef[(size_t)i * 2] = make_float2(0.f, 0.f);

    const float4* src; __nv_bfloat16 *dh, *dl; int j;
    if (i < 262144) { src = (const float4*)X; dh = g_xhi; dl = g_xlo; j = i; }
    else            { src = (const float4*)W; dh = g_whi; dl = g_wlo; j = i - 262144; }
    float4 v = src[j];
    __nv_bfloat16 h0 = __float2bfloat16(v.x), h1 = __float2bfloat16(v.y);
    __nv_bfloat16 h2 = __float2bfloat16(v.z), h3 = __float2bfloat16(v.w);
    __nv_bfloat16 l0 = __float2bfloat16(v.x - __bfloat162float(h0));
    __nv_bfloat16 l1 = __float2bfloat16(v.y - __bfloat162float(h1));
    __nv_bfloat16 l2 = __float2bfloat16(v.z - __bfloat162float(h2));
    __nv_bfloat16 l3 = __float2bfloat16(v.w - __bfloat162float(h3));
    __nv_bfloat162 hA = __nv_bfloat162(h0, h1), hB = __nv_bfloat162(h2, h3);
    __nv_bfloat162 lA = __nv_bfloat162(l0, l1), lB = __nv_bfloat162(l2, l3);
    uint2 ho, lo;
    ho.x = *(uint32_t*)&hA; ho.y = *(uint32_t*)&hB;
    lo.x = *(uint32_t*)&lA; lo.y = *(uint32_t*)&lB;
    *(uint2*)(dh + (size_t)j * 4) = ho;
    *(uint2*)(dl + (size_t)j * 4) = lo;

    // fused mean partials: blocks 0..31 -> (b = bx>>3, c = bx&7)
    if (blockIdx.x < 32) {
        int b = blockIdx.x >> 3, c = blockIdx.x & 7;
        const float* p0 = X + ((size_t)b * TQ + c * 32) * DM;
        for (int d = tid; d < DM; d += 256) {
            float s = 0.f;
            const float* p = p0 + d;
            #pragma unroll 8
            for (int t = 0; t < 32; ++t) s += p[(size_t)t * DM];
            g_xmp[b][c][d] = s;
        }
    }
}

// ---------------- K2: ef GEMM (blocks 0..511) + global context (512..515) --
// GEMM: 64x64 CTA tile, 128 thr (2x2 warps, 32x32/warp), BK=32, split-K=2,
// 3-stage cp.async ring (issue-before-compute), ldmatrix.x4, both kk-halves'
// fragments prefetched before mma. atomicAdd epilogue (2 adds/elem, determ).
#define BK     32
#define TSTR   40
#define KHALF  16
#define EF_TILE   (64 * TSTR)                 // bf16 elems per tile
#define EF_STAGE  (4 * EF_TILE)
#define EF_SMEM   (3 * EF_STAGE * 2)          // 61440 bytes

__global__ void __launch_bounds__(128) k_ef_mma(
    const float* __restrict__ gp_w, const float* __restrict__ gp_b,
    const float* __restrict__ g1_w, const float* __restrict__ g1_b,
    const float* __restrict__ g2_w, const float* __restrict__ g2_b)
{
    extern __shared__ __align__(16) char dsm[];
    int tid = threadIdx.x;

    // ---- fused k_global path (4 blocks) ----
    if (blockIdx.x >= 512) {
        float* xm   = (float*)dsm;        // 1024
        float* part = xm + DM;            // 128
        float* gctx = part + 128;         // 64
        float* g1s  = gctx + 64;          // 128
        int b = blockIdx.x - 512;
        if (b == 0 && tid < NEXP) g_ecnt[tid] = 0;
        for (int d = tid; d < DM; d += 128) {
            float s = 0.f;
            #pragma unroll
            for (int c = 0; c < 8; ++c) s += g_xmp[b][c][d];
            xm[d] = s * (1.0f / (float)TQ);
        }
        __syncthreads();
        {
            int j = tid >> 1, p = tid & 1;
            float s = 0.f;
            const float* w  = gp_w + (size_t)j * DM + p * 512;
            const float* xp = xm + p * 512;
            #pragma unroll 4
            for (int d = 0; d < 512; ++d) s += xp[d] * w[d];
            part[tid] = s;
        }
        __syncthreads();
        if (tid < DL) {
            float s = part[2*tid] + part[2*tid+1] + gp_b[tid];
            gctx[tid] = s;
            g_gctx[b * DL + tid] = s;
        }
        __syncthreads();
        {
            float s = g1_b[tid];
            const float* w = g1_w + tid * DL;
            #pragma unroll
            for (int d = 0; d < DL; ++d) s += gctx[d] * w[d];
            g1s[tid] = gelu_f(s);
        }
        __syncthreads();
        if (tid < NEXP) {
            float s = g2_b[tid];
            const float* w = g2_w + tid * 128;
            #pragma unroll
            for (int c = 0; c < 128; ++c) s += g1s[c] * w[c];
            g_gb[b * NEXP + tid] = s;
        }
        return;
    }

    // ---- GEMM path ----
    __nv_bfloat16* smb = (__nv_bfloat16*)dsm;
    auto tilep = [&](int s, int t4) { return smb + (s * 4 + t4) * EF_TILE; };

    int wid = tid >> 5, lane = tid & 31;
    int g = lane >> 2, t = lane & 3;
    int wm = (wid & 1) * 32, wn = (wid >> 1) * 32;
    int bx = blockIdx.x;
    int kz = bx >> 8, idx = bx & 255;
    int m0 = (idx >> 4) * 64, n0 = (idx & 15) * 64;
    int kbase = kz * (KHALF * BK);

    int loff = ((lane & 15) * TSTR + (lane >> 4) * 8) * 2;

    const __nv_bfloat16* tsrc[4] = {
        g_xhi + (size_t)m0 * DM + kbase, g_xlo + (size_t)m0 * DM + kbase,
        g_whi + (size_t)n0 * DM + kbase, g_wlo + (size_t)n0 * DM + kbase
    };

    float acc[2][4][4];
    #pragma unroll
    for (int mf = 0; mf < 2; ++mf)
        #pragma unroll
        for (int nf = 0; nf < 4; ++nf)
            #pragma unroll
            for (int q = 0; q < 4; ++q) acc[mf][nf][q] = 0.f;

    auto issue = [&](int c, int s) {
        int k0 = c * BK;
        #pragma unroll
        for (int t4 = 0; t4 < 4; ++t4) {
            const __nv_bfloat16* src = tsrc[t4] + k0;
            __nv_bfloat16* dt = tilep(s, t4);
            #pragma unroll
            for (int jj = 0; jj < 4; ++jj) {
                int u = tid + jj * 128;
                int r = u >> 3, c8 = u & 7;
                cp_async8(smem_u32(dt + r * TSTR + c8 * 4),
                          src + (size_t)r * DM + c8 * 4);
            }
        }
    };

    issue(0, 0); asm volatile("cp.async.commit_group;" ::: "memory");
    issue(1, 1); asm volatile("cp.async.commit_group;" ::: "memory");

    for (int c = 0; c < KHALF; ++c) {
        int bsel = c % 3;
        asm volatile("cp.async.wait_group 1;" ::: "memory");
        __syncthreads();
        if (c + 2 < KHALF) issue(c + 2, (c + 2) % 3);
        asm volatile("cp.async.commit_group;" ::: "memory");

        uint32_t baseAh = smem_u32(tilep(bsel, 0)) + loff;
        uint32_t baseAl = smem_u32(tilep(bsel, 1)) + loff;
        uint32_t baseBh = smem_u32(tilep(bsel, 2)) + loff;
        uint32_t baseBl = smem_u32(tilep(bsel, 3)) + loff;

        // prefetch BOTH kk-halves' fragments, then run all mma
        uint32_t a0h[2][4], a0l[2][4], b0h[2][4], b0l[2][4];
        uint32_t a1h[2][4], a1l[2][4], b1h[2][4], b1l[2][4];
        #pragma unroll
        for (int mf = 0; mf < 2; ++mf) {
            uint32_t ro = ((wm + mf * 16) * TSTR) * 2;
            ldsm4(a0h[mf], baseAh + ro);        ldsm4(a0l[mf], baseAl + ro);
            ldsm4(a1h[mf], baseAh + ro + 32);   ldsm4(a1l[mf], baseAl + ro + 32);
        }
        #pragma unroll
        for (int G = 0; G < 2; ++G) {
            uint32_t ro = ((wn + G * 16) * TSTR) * 2;
            ldsm4(b0h[G], baseBh + ro);         ldsm4(b0l[G], baseBl + ro);
            ldsm4(b1h[G], baseBh + ro + 32);    ldsm4(b1l[G], baseBl + ro + 32);
        }
        #pragma unroll
        for (int mf = 0; mf < 2; ++mf)
            #pragma unroll
            for (int nf = 0; nf < 4; ++nf) {
                int G = nf >> 1, o = nf & 1;
                mma_bf16(acc[mf][nf], a0h[mf], b0h[G][o], b0h[G][o + 2]);
                mma_bf16(acc[mf][nf], a0h[mf], b0l[G][o], b0l[G][o + 2]);
                mma_bf16(acc[mf][nf], a0l[mf], b0h[G][o], b0h[G][o + 2]);
            }
        #pragma unroll
        for (int mf = 0; mf < 2; ++mf)
            #pragma unroll
            for (int nf = 0; nf < 4; ++nf) {
                int G = nf >> 1, o = nf & 1;
                mma_bf16(acc[mf][nf], a1h[mf], b1h[G][o], b1h[G][o + 2]);
                mma_bf16(acc[mf][nf], a1h[mf], b1l[G][o], b1l[G][o + 2]);
                mma_bf16(acc[mf][nf], a1l[mf], b1h[G][o], b1h[G][o + 2]);
            }
    }

    #pragma unroll
    for (int mf = 0; mf < 2; ++mf) {
        int row = m0 + wm + mf * 16 + g;
        #pragma unroll
        for (int nf = 0; nf < 4; ++nf) {
            int col = n0 + wn + nf * 8 + 2 * t;
            atomicAdd(&g_ef[(size_t)(row    ) * DM + col    ], acc[mf][nf][0]);
            atomicAdd(&g_ef[(size_t)(row    ) * DM + col + 1], acc[mf][nf][1]);
            atomicAdd(&g_ef[(size_t)(row + 8) * DM + col    ], acc[mf][nf][2]);
            atomicAdd(&g_ef[(size_t)(row + 8) * DM + col + 1], acc[mf][nf][3]);
        }
    }
}

// ---------------- K3: per-token micro-transformer + routing ---------------
__global__ void __launch_bounds__(256)
k_token(const float* __restrict__ pos,
        const float* __restrict__ aw, const float* __restrict__ ab,
        const float* __restrict__ ow, const float* __restrict__ ob,
        const float* __restrict__ lnw, const float* __restrict__ lnb,
        const float* __restrict__ lsw, const float* __restrict__ lsb)
{
    __shared__ __align__(16) float seq[SEQL][DL];
    __shared__ __align__(16) float qkv[SEQL][192];
    __shared__ float sc[NH][SEQL][SEQL];
    __shared__ __align__(16) float ctx[SEQL][DL];
    __shared__ __align__(16) float hb[SEQL][DL];
    __shared__ float logits[NEXP];

    int n = blockIdx.x, tid = threadIdx.x;
    int b = n >> 8;

    for (int i = tid; i < NEXP * DL; i += 256)
        seq[1 + (i >> 6)][i & 63] = g_ef[(size_t)n * 1024 + i] + pos[i];
    if (tid < DL) seq[0][tid] = g_gctx[b * DL + tid];
    __syncthreads();

    if (tid < 192) {
        float acc[SEQL];
        #pragma unroll
        for (int i = 0; i < SEQL; ++i) acc[i] = 0.f;
        const float4* w4 = (const float4*)(aw + tid * DL);
        #pragma unroll
        for (int u = 0; u < 16; ++u) {
            float4 wv = w4[u];
            #pragma unroll
            for (int i = 0; i < SEQL; ++i) {
                float4 sv = *(const float4*)&seq[i][u * 4];
                acc[i] += wv.x * sv.x + wv.y * sv.y + wv.z * sv.z + wv.w * sv.w;
            }
        }
        float bias = ab[tid];
        #pragma unroll
        for (int i = 0; i < SEQL; ++i) qkv[i][tid] = acc[i] + bias;
    }
    __syncthreads();

    for (int idx = tid; idx < NH * SEQL * SEQL; idx += 256) {
        int h = idx / (SEQL * SEQL);
        int r = idx % (SEQL * SEQL);
        int i = r / SEQL, j = r % SEQL;
        const float4* qp = (const float4*)&qkv[i][h * HD];
        const float4* kp = (const float4*)&qkv[j][64 + h * HD];
        float s = 0.f;
        #pragma unroll
        for (int u = 0; u < 4; ++u) {
            float4 qv = qp[u], kv = kp[u];
            s += qv.x * kv.x + qv.y * kv.y + qv.z * kv.z + qv.w * kv.w;
        }
        sc[h][i][j] = s * 0.25f;
    }
    __syncthreads();

    if (tid < NH * SEQL) {
        int h = tid / SEQL, i = tid % SEQL;
        float m = -1e30f;
        #pragma unroll
        for (int j = 0; j < SEQL; ++j) m = fmaxf(m, sc[h][i][j]);
        float sum = 0.f;
        #pragma unroll
        for (int j = 0; j < SEQL; ++j) { float e = expf(sc[h][i][j] - m); sc[h][i][j] = e; sum += e; }
        float inv = 1.0f / sum;
        #pragma unroll
        for (int j = 0; j < SEQL; ++j) sc[h][i][j] *= inv;
    }
    __syncthreads();

    for (int idx = tid; idx < SEQL * DL; idx += 256) {
        int i = idx >> 6, d = idx & 63, h = d >> 4;
        float s = 0.f;
        #pragma unroll
        for (int j = 0; j < SEQL; ++j) s += sc[h][i][j] * qkv[j][128 + d];
        ctx[i][d] = s;
    }
    __syncthreads();

    if (tid < DL) {
        float acc[SEQL];
        #pragma unroll
        for (int i = 0; i < SEQL; ++i) acc[i] = 0.f;
        const float4* w4 = (const float4*)(ow + tid * DL);
        #pragma unroll
        for (int u = 0; u < 16; ++u) {
            float4 wv = w4[u];
            #pragma unroll
            for (int i = 0; i < SEQL; ++i) {
                float4 cv = *(const float4*)&ctx[i][u * 4];
                acc[i] += wv.x * cv.x + wv.y * cv.y + wv.z * cv.z + wv.w * cv.w;
            }
        }
        float bias = ob[tid];
        #pragma unroll
        for (int i = 0; i < SEQL; ++i) hb[i][tid] = acc[i] + bias + seq[i][tid];
    }
    __syncthreads();

    // LN rows 1..16 fused into logit: warp per 2 rows, shuffle reductions
    {
        int w = tid >> 5, lane = tid & 31;
        #pragma unroll
        for (int rr = 0; rr < 2; ++rr) {
            int i = 1 + (w << 1) + rr;
            float v0 = hb[i][lane], v1 = hb[i][lane + 32];
            float mu = wsum(v0 + v1) * (1.0f / DL);
            float d0 = v0 - mu, d1 = v1 - mu;
            float var = wsum(d0 * d0 + d1 * d1) * (1.0f / DL);
            float rstd = rsqrtf(var + 1e-5f);
            float lp = (d0 * rstd * lnw[lane]      + lnb[lane])      * lsw[lane]
                     + (d1 * rstd * lnw[lane + 32] + lnb[lane + 32]) * lsw[lane + 32];
            lp = wsum(lp);
            if (lane == 0) logits[i - 1] = lp + lsb[0] + g_gb[b * NEXP + (i - 1)];
        }
    }
    __syncthreads();

    if (tid == 0) {
        float m = -1e30f;
        #pragma unroll
        for (int e = 0; e < NEXP; ++e) m = fmaxf(m, logits[e]);
        float p[NEXP]; float sum = 0.f;
        #pragma unroll
        for (int e = 0; e < NEXP; ++e) { p[e] = expf(logits[e] - m); sum += p[e]; }
        float inv = 1.0f / sum;
        float best = -1e30f, sec = -1e30f; int bi = 0, si = 0;
        #pragma unroll
        for (int e = 0; e < NEXP; ++e) {
            float pe = p[e] * inv;
            g_probs[n * NEXP + e] = pe;
            if (pe > best)      { sec = best; si = bi; best = pe; bi = e; }
            else if (pe > sec)  { sec = pe; si = e; }
        }
        float s2 = best + sec;
        g_tw[2*n]   = best / s2;
        g_tw[2*n+1] = sec  / s2;
        g_ti[2*n]   = bi;
        g_ti[2*n+1] = si;
        int p0 = atomicAdd(&g_ecnt[bi], 1); g_elist[bi * NTOK + p0] = 2*n;
        int p1 = atomicAdd(&g_ecnt[si], 1); g_elist[si * NTOK + p1] = 2*n + 1;
    }
    __syncthreads();

    if (tid < 2 * DL) {
        int k = tid >> 6, d = tid & 63;
        int e = g_ti[2*n + k];
        g_act[(size_t)(2*n + k) * DL + d] = gelu_f(g_ef[(size_t)n * 1024 + e * DL + d]);
    }
}

// ---------------- K3b: flatten expert lists --------------------------------
__global__ void k_flat()
{
    __shared__ int off;
    int e = blockIdx.x;
    if (threadIdx.x == 0) {
        int o = 0;
        for (int i = 0; i < e; ++i) o += g_ecnt[i];
        off = o;
    }
    __syncthreads();
    int cnt = g_ecnt[e];
    for (int i = threadIdx.x; i < cnt; i += 256) {
        g_flat_a[off + i] = g_elist[e * NTOK + i];
        g_flat_e[off + i] = e;
    }
}

// ---------------- K4: expert up-projection -> atomicAdd out (+aux) ---------
__global__ void __launch_bounds__(256)
k_moe2(const float* __restrict__ w_up, float* __restrict__ out, int has_aux)
{
    __shared__ float acts[16][DL];
    __shared__ float wt[DL][64];
    __shared__ int sa[16];
    __shared__ int se[16];
    __shared__ float partial[NEXP];
    int tid = threadIdx.x;
    int base = blockIdx.x * 16;
    int m0 = blockIdx.y * 64;

    if (tid < 16) { sa[tid] = g_flat_a[base + tid]; se[tid] = g_flat_e[base + tid]; }
    __syncthreads();
    #pragma unroll
    for (int j = 0; j < 4; ++j) {
        int i = tid + j * 256;
        acts[i >> 6][i & 63] = g_act[(size_t)sa[i >> 6] * DL + (i & 63)];
    }
    __syncthreads();

    int s = 0;
    while (s < 16) {
        int e = se[s];
        int r = s + 1;
        while (r < 16 && se[r] == e) ++r;
        __syncthreads();
        #pragma unroll
        for (int j = 0; j < 16; ++j) {
            int idx = tid + j * 256;
            int d = idx >> 6, cc = idx & 63;
            wt[d][cc] = w_up[(((size_t)e << 6) + d) * 1024 + m0 + cc];
        }
        __syncthreads();
        for (int t0 = s; t0 < r; t0 += 4) {
            int t = t0 + (tid >> 6);
            if (t < r) {
                int col = tid & 63;
                float sum = 0.f;
                #pragma unroll
                for (int d = 0; d < DL; ++d) sum += acts[t][d] * wt[d][col];
                int a = sa[t];
                atomicAdd(&out[(size_t)(a >> 1) * 1024 + m0 + col], g_tw[a] * sum);
            }
        }
        s = r;
    }

    // fused aux loss (block 0,0 only; deterministic fixed-order reduction)
    if (has_aux && blockIdx.x == 0 && blockIdx.y == 0) {
        int w = tid >> 5, lane = tid & 31;
        for (int ee = w; ee < NEXP; ee += 8) {
            float psum = 0.f; int ccnt = 0;
            for (int n = lane; n < NTOK; n += 32) {
                psum += g_probs[n * NEXP + ee];
                ccnt += (g_ti[2*n] == ee) + (g_ti[2*n+1] == ee);
            }
            #pragma unroll
            for (int o = 16; o; o >>= 1) {
                psum += __shfl_down_sync(0xffffffffu, psum, o);
                ccnt += __shfl_down_sync(0xffffffffu, ccnt, o);
            }
            if (lane == 0) partial[ee] = psum * (float)ccnt;
        }
        __syncthreads();
        if (tid == 0) {
            float ssum = 0.f;
            #pragma unroll
            for (int e = 0; e < NEXP; ++e) ssum += partial[e];
            out[NTOK * 1024] = ssum * ((float)NEXP / ((float)NTOK * (float)NTOK));
        }
    }
}

// ---------------- launch ---------------------------------------------------
extern "C" void kernel_launch(void* const* d_in, const int* in_sizes, int n_in,
                              void* d_out, int out_size)
{
    const float* x      = (const float*)d_in[0];
    const float* w_down = (const float*)d_in[1];
    const float* pos    = (const float*)d_in[2];
    const float* gp_w   = (const float*)d_in[3];
    const float* gp_b   = (const float*)d_in[4];
    const float* aw     = (const float*)d_in[5];
    const float* ab     = (const float*)d_in[6];
    const float* ow     = (const float*)d_in[7];
    const float* ob     = (const float*)d_in[8];
    const float* lnw    = (const float*)d_in[9];
    const float* lnb    = (const float*)d_in[10];
    const float* lsw    = (const float*)d_in[11];
    const float* lsb    = (const float*)d_in[12];
    const float* g1w    = (const float*)d_in[13];
    const float* g1b    = (const float*)d_in[14];
    const float* g2w    = (const float*)d_in[15];
    const float* g2b    = (const float*)d_in[16];
    const float* wup    = (const float*)d_in[17];
    float* out = (float*)d_out;

    static int attr_done = 0;
    if (!attr_done) {
        cudaFuncSetAttribute(k_ef_mma, cudaFuncAttributeMaxDynamicSharedMemorySize, EF_SMEM);
        attr_done = 1;
    }

    int has_aux = (out_size > NTOK * 1024) ? 1 : 0;

    cudaMemsetAsync(d_out, 0, (size_t)out_size * sizeof(float));
    k_split  <<<2048, 256>>>(x, w_down);
    k_ef_mma <<<516, 128, EF_SMEM>>>(gp_w, gp_b, g1w, g1b, g2w, g2b);
    k_token  <<<NTOK, 256>>>(pos, aw, ab, ow, ob, lnw, lnb, lsw, lsb);
    k_flat   <<<NEXP, 256>>>();
    k_moe2   <<<dim3(NASSIGN / 16, 16), 256>>>(wup, out, has_aux);
}